// round 4
// baseline (speedup 1.0000x reference)
#include <cuda_runtime.h>
#include <math.h>

// ---------------- problem constants ----------------
#define BATCH   64
#define SEQ     512
#define EMB     256
#define HID     512
#define GATES   2048           // 4*HID
#define VOCAB   50257
#define NBLK    128            // persistent LSTM grid (<=148 SMs, 1 block/SM)

// ---------------- device scratch (static, no allocs) ----------------
__device__ float g_Z[(size_t)SEQ * BATCH * GATES];   // 256 MB: x@Wi + b, [s][b][4H]
__device__ float g_hT[2][HID * BATCH];               // hidden state, k-major [u][b]
__device__ float g_y1[BATCH * HID];
__device__ float g_y2[BATCH * HID];
__device__ float g_logits[(size_t)BATCH * VOCAB];
__device__ unsigned g_flags[NBLK];                   // per-block step flags

// ---------------- packed f32x2 helpers (FFMA2 path, sm_100+) --------------
__device__ __forceinline__ unsigned long long fma2(unsigned long long a,
                                                   unsigned long long b,
                                                   unsigned long long c)
{
    unsigned long long d;
    asm("fma.rn.f32x2 %0, %1, %2, %3;" : "=l"(d) : "l"(a), "l"(b), "l"(c));
    return d;
}
__device__ __forceinline__ unsigned long long pack2(float x)
{
    unsigned long long d;
    unsigned u = __float_as_uint(x);
    asm("mov.b64 %0, {%1, %1};" : "=l"(d) : "r"(u));
    return d;
}
__device__ __forceinline__ float lo2(unsigned long long v) { return __uint_as_float((unsigned)v); }
__device__ __forceinline__ float hi2(unsigned long long v) { return __uint_as_float((unsigned)(v >> 32)); }

__device__ __forceinline__ float sigmoidf_(float x)
{
    return 1.0f / (1.0f + __expf(-x));
}

// ---------------- kernel 0: reset barrier flags (per launch) --------------
__global__ void reset_kernel()
{
    if (threadIdx.x < NBLK) g_flags[threadIdx.x] = 0u;
}

// ---------------- kernel 1: Z = gather(emb, inputs) @ Wi + b --------------
// 128x128 block tile, K-chunks of 16, 8x8 thread tile via f32x2.
__global__ void __launch_bounds__(256, 2)
embed_gemm_kernel(const int* __restrict__ inputs, const float* __restrict__ emb,
                  const float* __restrict__ Wi, const float* __restrict__ bias)
{
    __shared__ float As[128][17];
    __shared__ float Bs[16][132];

    const int t  = threadIdx.x;
    const int mt = blockIdx.y;
    const int nt = blockIdx.x;
    const int tx = t & 15;
    const int ty = t >> 4;

    const int ra   = t >> 1;
    const int koff = (t & 1) * 8;
    const int rowg = mt * 128 + ra;
    const int s    = rowg >> 6;
    const int b    = rowg & 63;
    const float* erow = emb + (size_t)inputs[b * SEQ + s] * EMB;

    const int bkr  = t >> 4;
    const int bcol = (t & 15) * 8;

    unsigned long long acc[8][4];
#pragma unroll
    for (int i = 0; i < 8; ++i)
#pragma unroll
        for (int j = 0; j < 4; ++j) acc[i][j] = 0ULL;

    for (int k0 = 0; k0 < EMB; k0 += 16) {
        {
            float4 a0 = *(const float4*)(erow + k0 + koff);
            float4 a1 = *(const float4*)(erow + k0 + koff + 4);
            As[ra][koff + 0] = a0.x; As[ra][koff + 1] = a0.y;
            As[ra][koff + 2] = a0.z; As[ra][koff + 3] = a0.w;
            As[ra][koff + 4] = a1.x; As[ra][koff + 5] = a1.y;
            As[ra][koff + 6] = a1.z; As[ra][koff + 7] = a1.w;
        }
        {
            const float* wsrc = Wi + (size_t)(k0 + bkr) * GATES + nt * 128 + bcol;
            float4 b0v = *(const float4*)(wsrc);
            float4 b1v = *(const float4*)(wsrc + 4);
            *(float4*)&Bs[bkr][bcol]     = b0v;
            *(float4*)&Bs[bkr][bcol + 4] = b1v;
        }
        __syncthreads();

#pragma unroll
        for (int k = 0; k < 16; ++k) {
            unsigned long long pa[8];
#pragma unroll
            for (int i = 0; i < 4; ++i) {
                pa[i]     = pack2(As[ty * 4 + i][k]);
                pa[i + 4] = pack2(As[64 + ty * 4 + i][k]);
            }
            ulonglong2 b0v = *(const ulonglong2*)&Bs[k][tx * 4];
            ulonglong2 b1v = *(const ulonglong2*)&Bs[k][64 + tx * 4];
#pragma unroll
            for (int i = 0; i < 8; ++i) {
                acc[i][0] = fma2(pa[i], b0v.x, acc[i][0]);
                acc[i][1] = fma2(pa[i], b0v.y, acc[i][1]);
                acc[i][2] = fma2(pa[i], b1v.x, acc[i][2]);
                acc[i][3] = fma2(pa[i], b1v.y, acc[i][3]);
            }
        }
        __syncthreads();
    }

    float4 bb0 = *(const float4*)(bias + nt * 128 + tx * 4);
    float4 bb1 = *(const float4*)(bias + nt * 128 + 64 + tx * 4);
#pragma unroll
    for (int i = 0; i < 8; ++i) {
        int row = mt * 128 + ((i < 4) ? (ty * 4 + i) : (64 + ty * 4 + i - 4));
        float* zr = g_Z + (size_t)row * GATES + nt * 128;
        float4 v0, v1;
        v0.x = lo2(acc[i][0]) + bb0.x; v0.y = hi2(acc[i][0]) + bb0.y;
        v0.z = lo2(acc[i][1]) + bb0.z; v0.w = hi2(acc[i][1]) + bb0.w;
        v1.x = lo2(acc[i][2]) + bb1.x; v1.y = hi2(acc[i][2]) + bb1.y;
        v1.z = lo2(acc[i][3]) + bb1.z; v1.w = hi2(acc[i][3]) + bb1.w;
        *(float4*)(zr + tx * 4)      = v0;
        *(float4*)(zr + 64 + tx * 4) = v1;
    }
}

// ---------------- kernel 2: persistent LSTM over 512 steps ----------------
// 128 blocks x 256 threads, 1/SM. Block owns 4 units x 64 batches, k-split 4.
// tid = [bg:4][u:2][kc:2]  ->  kc in lane bits => shuffle reduction.
// Two-phase staging: phase A = first 64 k of each kc-strip, B = second 64.
// smem: h_s skewed [512][64] (+8 fl per kc) and Whs skewed [512][4] ull2.
#define LSTM_SMEM 164096

__global__ void __launch_bounds__(256, 1)
lstm_kernel(const float* __restrict__ Wh)
{
    extern __shared__ float sm[];
    float*      h_s = sm;                              // skewed [k][64]
    ulonglong2* Whs = (ulonglong2*)(sm + 32800);       // skewed [k][4u]

    const int tid = threadIdx.x;
    const int kc  = tid & 3;
    const int u   = (tid >> 2) & 3;
    const int bg  = tid >> 4;            // 0..15
    const int b0  = bg * 4;
    const int uu  = blockIdx.x * 4 + u;

    // stage Wh slice once: Whs[k*4+u2+(k>>7)*2] = {(wi,wf),(wg,wo)}
    for (int i = tid; i < HID * 4; i += 256) {
        int k = i >> 2, u2 = i & 3;
        const float* w = Wh + (size_t)k * GATES + blockIdx.x * 4 + u2;
        float4 v = make_float4(w[0], w[512], w[1024], w[1536]);
        Whs[i + (k >> 7) * 2] = *(ulonglong2*)&v;
    }

    float c[4] = {0.f, 0.f, 0.f, 0.f};   // cell state (kc==0 lanes own it)
    __syncthreads();

    const ulonglong2* wp = Whs + kc * 514 + u;                 // wp[i*4]
    const float4*     hp = (const float4*)h_s + kc * 2050 + bg; // hp[i*16]
    float4*           hsm = (float4*)h_s;

    for (int s = 0; s < SEQ; ++s) {
        const float4* src = (const float4*)g_hT[s & 1];

        // ---- phase A staging: first 64 k of each kc strip ----
        if (s > 0) {
            float4 ra[16];
#pragma unroll
            for (int q = 0; q < 16; ++q)
                ra[q] = __ldcg(src + tid + (q >> 2) * 2048 + (q & 3) * 256);
#pragma unroll
            for (int q = 0; q < 16; ++q)
                hsm[tid + (q >> 2) * 2050 + (q & 3) * 256] = ra[q];
        }

        // Z gates (reducer lanes), issued early to hide latency
        float zv[16];
        if (kc == 0) {
            const float* zb = g_Z + (size_t)s * BATCH * GATES + uu;
#pragma unroll
            for (int bi = 0; bi < 4; ++bi) {
                const float* z = zb + (size_t)(b0 + bi) * GATES;
                zv[bi * 4 + 0] = __ldcg(z);
                zv[bi * 4 + 1] = __ldcg(z + 512);
                zv[bi * 4 + 2] = __ldcg(z + 1024);
                zv[bi * 4 + 3] = __ldcg(z + 1536);
            }
        }
        __syncthreads();   // phase A visible

        unsigned long long aif[4] = {0, 0, 0, 0};
        unsigned long long ago[4] = {0, 0, 0, 0};

        if (s > 0) {
            // issue phase B loads (held in regs across phase-A compute)
            float4 rb[16];
#pragma unroll
            for (int q = 0; q < 16; ++q)
                rb[q] = __ldcg(src + tid + (q >> 2) * 2048 + (q & 3) * 256 + 1024);

            // compute phase A: i = 0..63
#pragma unroll 8
            for (int i = 0; i < 64; ++i) {
                ulonglong2 w  = wp[i * 4];
                float4     hv = hp[i * 16];
                unsigned long long p;
                p = pack2(hv.x); aif[0] = fma2(p, w.x, aif[0]); ago[0] = fma2(p, w.y, ago[0]);
                p = pack2(hv.y); aif[1] = fma2(p, w.x, aif[1]); ago[1] = fma2(p, w.y, ago[1]);
                p = pack2(hv.z); aif[2] = fma2(p, w.x, aif[2]); ago[2] = fma2(p, w.y, ago[2]);
                p = pack2(hv.w); aif[3] = fma2(p, w.x, aif[3]); ago[3] = fma2(p, w.y, ago[3]);
            }

            // store phase B to smem
#pragma unroll
            for (int q = 0; q < 16; ++q)
                hsm[tid + (q >> 2) * 2050 + (q & 3) * 256 + 1024] = rb[q];
        }
        __syncthreads();   // phase B visible

        if (s > 0) {
#pragma unroll 8
            for (int i = 64; i < 128; ++i) {
                ulonglong2 w  = wp[i * 4];
                float4     hv = hp[i * 16];
                unsigned long long p;
                p = pack2(hv.x); aif[0] = fma2(p, w.x, aif[0]); ago[0] = fma2(p, w.y, ago[0]);
                p = pack2(hv.y); aif[1] = fma2(p, w.x, aif[1]); ago[1] = fma2(p, w.y, ago[1]);
                p = pack2(hv.z); aif[2] = fma2(p, w.x, aif[2]); ago[2] = fma2(p, w.y, ago[2]);
                p = pack2(hv.w); aif[3] = fma2(p, w.x, aif[3]); ago[3] = fma2(p, w.y, ago[3]);
            }
        }

        // ---- butterfly reduce over the 4 kc lanes (lane bits 0..1) ----
        float fi[4], ff[4], fg_[4], fo[4];
#pragma unroll
        for (int bi = 0; bi < 4; ++bi) {
            fi[bi] = lo2(aif[bi]); ff[bi] = hi2(aif[bi]);
            fg_[bi] = lo2(ago[bi]); fo[bi] = hi2(ago[bi]);
        }
#pragma unroll
        for (int d = 1; d <= 2; d <<= 1) {
#pragma unroll
            for (int bi = 0; bi < 4; ++bi) {
                fi[bi]  += __shfl_xor_sync(0xffffffffu, fi[bi],  d);
                ff[bi]  += __shfl_xor_sync(0xffffffffu, ff[bi],  d);
                fg_[bi] += __shfl_xor_sync(0xffffffffu, fg_[bi], d);
                fo[bi]  += __shfl_xor_sync(0xffffffffu, fo[bi],  d);
            }
        }

        if (kc == 0) {
            float hv[4];
#pragma unroll
            for (int bi = 0; bi < 4; ++bi) {
                float ai = zv[bi * 4 + 0] + fi[bi];
                float af = zv[bi * 4 + 1] + ff[bi];
                float ag = zv[bi * 4 + 2] + fg_[bi];
                float ao = zv[bi * 4 + 3] + fo[bi];
                float ig = sigmoidf_(ai);
                float fg2 = sigmoidf_(af);
                float gg = tanhf(ag);
                float og = sigmoidf_(ao);
                c[bi] = fg2 * c[bi] + ig * gg;
                hv[bi] = og * tanhf(c[bi]);
            }
            *(float4*)(g_hT[(s + 1) & 1] + uu * 64 + b0) =
                make_float4(hv[0], hv[1], hv[2], hv[3]);
            __threadfence();     // h globally visible before flag
        }
        __syncthreads();

        // ---- flag-array grid barrier ----
        if (tid == 0) {
            unsigned val = (unsigned)(s + 1);
            asm volatile("st.release.gpu.global.u32 [%0], %1;"
                         :: "l"(&g_flags[blockIdx.x]), "r"(val) : "memory");
        }
        if (tid < NBLK) {
            unsigned target = (unsigned)(s + 1), v;
            do {
                asm volatile("ld.acquire.gpu.global.u32 %0, [%1];"
                             : "=r"(v) : "l"(&g_flags[tid]));
            } while (v < target);
        }
        __syncthreads();
    }
}

// ---------------- kernels 3/4: y = tanh(x @ W + bias), 64x512 --------------
// SK/SB: element strides of x along k and b (fc1 reads k-major g_hT).
template<int SK, int SB>
__global__ void __launch_bounds__(256)
fc_tanh_kernel(const float* __restrict__ x, const float* __restrict__ W,
               const float* __restrict__ bias, float* __restrict__ y)
{
    int o = blockIdx.x * blockDim.x + threadIdx.x;
    int b = o >> 9, j = o & 511;
    const float* xp = x + b * SB;
    float a0 = 0.f, a1 = 0.f, a2 = 0.f, a3 = 0.f;
#pragma unroll 4
    for (int k = 0; k < HID; k += 4) {
        a0 += xp[(k + 0) * SK] * W[(size_t)(k + 0) * HID + j];
        a1 += xp[(k + 1) * SK] * W[(size_t)(k + 1) * HID + j];
        a2 += xp[(k + 2) * SK] * W[(size_t)(k + 2) * HID + j];
        a3 += xp[(k + 3) * SK] * W[(size_t)(k + 3) * HID + j];
    }
    y[o] = tanhf((a0 + a1) + (a2 + a3) + bias[j]);
}

// ---------------- kernel 5: logits = y2 @ W3 + b3 ----------------
__global__ void __launch_bounds__(128)
logits_kernel(const float* __restrict__ y, const float* __restrict__ W3,
              const float* __restrict__ b3, float* __restrict__ out)
{
    __shared__ float ys[128][68];
    const int j = blockIdx.x * 128 + threadIdx.x;

    float acc[64];
#pragma unroll
    for (int b = 0; b < 64; ++b) acc[b] = 0.0f;

    for (int kc = 0; kc < HID; kc += 128) {
        __syncthreads();
        for (int q = threadIdx.x; q < 128 * 64; q += 128) {
            int b = q >> 7, k = q & 127;
            ys[k][b] = y[b * HID + kc + k];
        }
        __syncthreads();
        if (j < VOCAB) {
#pragma unroll 4
            for (int k = 0; k < 128; ++k) {
                float w = W3[(size_t)(kc + k) * VOCAB + j];
                const float4* yr = (const float4*)&ys[k][0];
#pragma unroll
                for (int b4 = 0; b4 < 16; ++b4) {
                    float4 v = yr[b4];
                    acc[b4 * 4 + 0] += v.x * w;
                    acc[b4 * 4 + 1] += v.y * w;
                    acc[b4 * 4 + 2] += v.z * w;
                    acc[b4 * 4 + 3] += v.w * w;
                }
            }
        }
    }
    if (j < VOCAB) {
        float bb = b3[j];
#pragma unroll
        for (int b = 0; b < 64; ++b)
            out[(size_t)b * VOCAB + j] = acc[b] + bb;
    }
}

// ---------------- kernel 6: row-wise log_softmax ----------------
__global__ void __launch_bounds__(1024)
logsoftmax_kernel(const float* __restrict__ logits, float* __restrict__ out)
{
    __shared__ float red[32];
    const int b = blockIdx.x;
    const float* row  = logits + (size_t)b * VOCAB;
    float*       orow = out    + (size_t)b * VOCAB;
    const int tid = threadIdx.x;

    float m = -1e30f;
    for (int j = tid; j < VOCAB; j += 1024) m = fmaxf(m, row[j]);
#pragma unroll
    for (int o = 16; o; o >>= 1) m = fmaxf(m, __shfl_xor_sync(0xffffffffu, m, o));
    if ((tid & 31) == 0) red[tid >> 5] = m;
    __syncthreads();
    if (tid < 32) {
        float v = red[tid];
#pragma unroll
        for (int o = 16; o; o >>= 1) v = fmaxf(v, __shfl_xor_sync(0xffffffffu, v, o));
        red[tid] = v;
    }
    __syncthreads();
    m = red[0];

    float sum = 0.0f;
    for (int j = tid; j < VOCAB; j += 1024) sum += __expf(row[j] - m);
#pragma unroll
    for (int o = 16; o; o >>= 1) sum += __shfl_xor_sync(0xffffffffu, sum, o);
    __syncthreads();
    if ((tid & 31) == 0) red[tid >> 5] = sum;
    __syncthreads();
    if (tid < 32) {
        float v = red[tid];
#pragma unroll
        for (int o = 16; o; o >>= 1) v += __shfl_xor_sync(0xffffffffu, v, o);
        red[tid] = v;
    }
    __syncthreads();
    float lse = m + logf(red[0]);

    for (int j = tid; j < VOCAB; j += 1024) orow[j] = row[j] - lse;
}

// ---------------- launch ----------------
extern "C" void kernel_launch(void* const* d_in, const int* in_sizes, int n_in,
                              void* d_out, int out_size)
{
    const int*   inputs = (const int*)  d_in[0];
    const float* emb    = (const float*)d_in[1];
    const float* Wi     = (const float*)d_in[2];
    const float* Wh     = (const float*)d_in[3];
    const float* bvec   = (const float*)d_in[4];
    const float* W1     = (const float*)d_in[5];
    const float* b1     = (const float*)d_in[6];
    const float* W2     = (const float*)d_in[7];
    const float* b2     = (const float*)d_in[8];
    const float* W3     = (const float*)d_in[9];
    const float* b3     = (const float*)d_in[10];
    float* out = (float*)d_out;

    void *p_h = 0, *p_y1 = 0, *p_y2 = 0, *p_lg = 0;
    cudaGetSymbolAddress(&p_h,  g_hT);     // final h in g_hT[0], k-major
    cudaGetSymbolAddress(&p_y1, g_y1);
    cudaGetSymbolAddress(&p_y2, g_y2);
    cudaGetSymbolAddress(&p_lg, g_logits);

    // 0. reset barrier flags (replay-safe)
    reset_kernel<<<1, 128>>>();

    // 1. Z = emb[inputs] @ Wi + b  (time-parallel)
    embed_gemm_kernel<<<dim3(GATES / 128, (SEQ * BATCH) / 128), 256>>>(inputs, emb, Wi, bvec);

    // 2. persistent LSTM recurrence
    cudaFuncSetAttribute(lstm_kernel, cudaFuncAttributeMaxDynamicSharedMemorySize, LSTM_SMEM);
    lstm_kernel<<<NBLK, 256, LSTM_SMEM>>>(Wh);

    // 3/4. dense tanh layers (fc1 reads k-major h)
    fc_tanh_kernel<64, 1><<<128, 256>>>((const float*)p_h,  W1, b1, (float*)p_y1);
    fc_tanh_kernel<1, 512><<<128, 256>>>((const float*)p_y1, W2, b2, (float*)p_y2);

    // 5. vocab projection
    logits_kernel<<<(VOCAB + 127) / 128, 128>>>((const float*)p_y2, W3, b3, (float*)p_lg);

    // 6. log_softmax
    logsoftmax_kernel<<<BATCH, 1024>>>((const float*)p_lg, out);
}

// round 5
// speedup vs baseline: 1.6165x; 1.6165x over previous
#include <cuda_runtime.h>
#include <math.h>

// ---------------- problem constants ----------------
#define BATCH   64
#define SEQ     512
#define EMB     256
#define HID     512
#define GATES   2048           // 4*HID
#define VOCAB   50257
#define NBLK    128            // persistent LSTM grid (<=148 SMs, 1 block/SM)

// ---------------- device scratch (static, no allocs) ----------------
__device__ float g_Z[(size_t)SEQ * BATCH * GATES];   // 256 MB: x@Wi + b, [s][b][4H]
__device__ float g_hT[2][HID * BATCH];               // hidden state, k-major [u][b]
__device__ float g_y1[BATCH * HID];
__device__ float g_y2[BATCH * HID];
__device__ float g_logits[(size_t)BATCH * VOCAB];
__device__ unsigned g_bar_cnt   = 0;
__device__ unsigned g_bar_sense = 0;

// ---------------- packed f32x2 helpers (FFMA2 path, sm_100+) --------------
__device__ __forceinline__ unsigned long long fma2(unsigned long long a,
                                                   unsigned long long b,
                                                   unsigned long long c)
{
    unsigned long long d;
    asm("fma.rn.f32x2 %0, %1, %2, %3;" : "=l"(d) : "l"(a), "l"(b), "l"(c));
    return d;
}
__device__ __forceinline__ unsigned long long pack2(float x)
{
    unsigned long long d;
    unsigned u = __float_as_uint(x);
    asm("mov.b64 %0, {%1, %1};" : "=l"(d) : "r"(u));
    return d;
}
__device__ __forceinline__ float lo2(unsigned long long v) { return __uint_as_float((unsigned)v); }
__device__ __forceinline__ float hi2(unsigned long long v) { return __uint_as_float((unsigned)(v >> 32)); }

__device__ __forceinline__ float sigmoidf_(float x)
{
    return 1.0f / (1.0f + __expf(-x));
}

// ---------------- cp.async helpers ----------------
__device__ __forceinline__ void cp16(unsigned dst_u32, const void* src)
{
    asm volatile("cp.async.cg.shared.global [%0], [%1], 16;"
                 :: "r"(dst_u32), "l"(src) : "memory");
}
__device__ __forceinline__ void cp_commit()
{
    asm volatile("cp.async.commit_group;" ::: "memory");
}
__device__ __forceinline__ void cp_wait1()
{
    asm volatile("cp.async.wait_group 1;" ::: "memory");
}
__device__ __forceinline__ void cp_wait0()
{
    asm volatile("cp.async.wait_group 0;" ::: "memory");
}

// ---------------- grid barrier (R2-proven: single flag, one poller) --------
__device__ __forceinline__ void grid_barrier(unsigned &sense)
{
    __syncthreads();
    if (threadIdx.x == 0) {
        sense ^= 1u;
        __threadfence();
        if (atomicAdd(&g_bar_cnt, 1u) == NBLK - 1u) {
            atomicExch(&g_bar_cnt, 0u);
            __threadfence();
            atomicExch(&g_bar_sense, sense);
        } else {
            while (((volatile unsigned*)&g_bar_sense)[0] != sense) { }
            __threadfence();
        }
    }
    __syncthreads();
}

// ---------------- kernel 1: Z = gather(emb, inputs) @ Wi + b --------------
// (R2-proven, unchanged) 128x128 tile, K-chunks of 16, 8x8 thread tile, f32x2.
__global__ void __launch_bounds__(256, 2)
embed_gemm_kernel(const int* __restrict__ inputs, const float* __restrict__ emb,
                  const float* __restrict__ Wi, const float* __restrict__ bias)
{
    __shared__ float As[128][17];
    __shared__ float Bs[16][132];

    const int t  = threadIdx.x;
    const int mt = blockIdx.y;
    const int nt = blockIdx.x;
    const int tx = t & 15;
    const int ty = t >> 4;

    const int ra   = t >> 1;
    const int koff = (t & 1) * 8;
    const int rowg = mt * 128 + ra;
    const int s    = rowg >> 6;
    const int b    = rowg & 63;
    const float* erow = emb + (size_t)inputs[b * SEQ + s] * EMB;

    const int bkr  = t >> 4;
    const int bcol = (t & 15) * 8;

    unsigned long long acc[8][4];
#pragma unroll
    for (int i = 0; i < 8; ++i)
#pragma unroll
        for (int j = 0; j < 4; ++j) acc[i][j] = 0ULL;

    for (int k0 = 0; k0 < EMB; k0 += 16) {
        {
            float4 a0 = *(const float4*)(erow + k0 + koff);
            float4 a1 = *(const float4*)(erow + k0 + koff + 4);
            As[ra][koff + 0] = a0.x; As[ra][koff + 1] = a0.y;
            As[ra][koff + 2] = a0.z; As[ra][koff + 3] = a0.w;
            As[ra][koff + 4] = a1.x; As[ra][koff + 5] = a1.y;
            As[ra][koff + 6] = a1.z; As[ra][koff + 7] = a1.w;
        }
        {
            const float* wsrc = Wi + (size_t)(k0 + bkr) * GATES + nt * 128 + bcol;
            float4 b0v = *(const float4*)(wsrc);
            float4 b1v = *(const float4*)(wsrc + 4);
            *(float4*)&Bs[bkr][bcol]     = b0v;
            *(float4*)&Bs[bkr][bcol + 4] = b1v;
        }
        __syncthreads();

#pragma unroll
        for (int k = 0; k < 16; ++k) {
            unsigned long long pa[8];
#pragma unroll
            for (int i = 0; i < 4; ++i) {
                pa[i]     = pack2(As[ty * 4 + i][k]);
                pa[i + 4] = pack2(As[64 + ty * 4 + i][k]);
            }
            ulonglong2 b0v = *(const ulonglong2*)&Bs[k][tx * 4];
            ulonglong2 b1v = *(const ulonglong2*)&Bs[k][64 + tx * 4];
#pragma unroll
            for (int i = 0; i < 8; ++i) {
                acc[i][0] = fma2(pa[i], b0v.x, acc[i][0]);
                acc[i][1] = fma2(pa[i], b0v.y, acc[i][1]);
                acc[i][2] = fma2(pa[i], b1v.x, acc[i][2]);
                acc[i][3] = fma2(pa[i], b1v.y, acc[i][3]);
            }
        }
        __syncthreads();
    }

    float4 bb0 = *(const float4*)(bias + nt * 128 + tx * 4);
    float4 bb1 = *(const float4*)(bias + nt * 128 + 64 + tx * 4);
#pragma unroll
    for (int i = 0; i < 8; ++i) {
        int row = mt * 128 + ((i < 4) ? (ty * 4 + i) : (64 + ty * 4 + i - 4));
        float* zr = g_Z + (size_t)row * GATES + nt * 128;
        float4 v0, v1;
        v0.x = lo2(acc[i][0]) + bb0.x; v0.y = hi2(acc[i][0]) + bb0.y;
        v0.z = lo2(acc[i][1]) + bb0.z; v0.w = hi2(acc[i][1]) + bb0.w;
        v1.x = lo2(acc[i][2]) + bb1.x; v1.y = hi2(acc[i][2]) + bb1.y;
        v1.z = lo2(acc[i][3]) + bb1.z; v1.w = hi2(acc[i][3]) + bb1.w;
        *(float4*)(zr + tx * 4)      = v0;
        *(float4*)(zr + 64 + tx * 4) = v1;
    }
}

// ---------------- kernel 2: persistent LSTM over 512 steps ----------------
// 128 blocks = 64 unit-groups x 2 batch-halves; block = 8 units x 32 batches.
// tid bits: [0:2)=kc, [2)=u_low, [3:5)=bg_low, [5:7)=u_high, [7)=bg_high.
// Thread: 1 unit, 4 batches, K-strip of 128 (k-split 4) -> 1024 fma2/step.
// Reduction: shuffle-xor over kc lanes. Staging: two-phase cp.async.
// smem: h_s4 [4102] float4 (k-major, strip-skew 2) + Whs [4102] ull2.
#define LSTM_SMEM 131264

__global__ void __launch_bounds__(256, 1)
lstm_kernel(const float* __restrict__ Wh)
{
    extern __shared__ float sm[];
    float4*     h_s4 = (float4*)sm;                  // [k*8 + (k>>7)*2 + c]
    ulonglong2* Whs  = (ulonglong2*)(sm + 4102 * 4); // [k*8 + (k>>7)*2 + u]

    const int tid = threadIdx.x;
    const int kc  = tid & 3;
    const int u   = (((tid >> 5) & 3) << 1) | ((tid >> 2) & 1);   // 0..7
    const int bg  = (((tid >> 7) & 1) << 2) | ((tid >> 3) & 3);   // 0..7
    const int ub  = blockIdx.x >> 1;       // unit group 0..63
    const int bh  = blockIdx.x & 1;        // batch half
    const int uu  = ub * 8 + u;            // global unit
    const int gb0 = bh * 32 + bg * 4;      // first global batch of this thread

    const unsigned h_s_u32 = (unsigned)__cvta_generic_to_shared(h_s4);

    // stage Wh slice once: Whs[k*8+u2+(k>>7)*2] = {(wi,wf),(wg,wo)}, col=ub*8+u2
    for (int i = tid; i < HID * 8; i += 256) {
        int k = i >> 3, u2 = i & 7;
        const float* w = Wh + (size_t)k * GATES + ub * 8 + u2;
        float4 v = make_float4(w[0], w[512], w[1024], w[1536]);
        Whs[i + ((i >> 10) << 1)] = *(ulonglong2*)&v;
    }
    // zero h_s (step 0 multiplies against nothing; loop guarded by s>0)
    {
        float4 z4 = make_float4(0.f, 0.f, 0.f, 0.f);
        for (int j = tid; j < 4102; j += 256) h_s4[j] = z4;
    }

    float c[4] = {0.f, 0.f, 0.f, 0.f};     // cell state (kc==0 lanes own it)
    unsigned sense = 0;
    __syncthreads();

    const ulonglong2* wp = Whs + kc * 1026 + u;    // element i: wp[i*8]
    const float4*     hp = h_s4 + kc * 1026 + bg;  // element i: hp[i*8]

    for (int s = 0; s < SEQ; ++s) {
        // ---- two-phase cp.async staging of h_{s-1} (this block's 32 batches)
        if (s > 0) {
            const float* srcb = g_hT[s & 1] + bh * 32;
            // phase A: k-positions [0,64) of every kc strip -> (j&3) in {0,1}
#pragma unroll
            for (int j = 0; j < 16; ++j) {
                if ((j & 3) < 2) {
                    int q   = tid + j * 256;            // chunk id
                    int dst = q + ((q >> 10) << 1);     // skewed float4 index
                    cp16(h_s_u32 + dst * 16, srcb + (q >> 3) * 64 + (q & 7) * 4);
                }
            }
            cp_commit();
            // phase B: k-positions [64,128) of every strip
#pragma unroll
            for (int j = 0; j < 16; ++j) {
                if ((j & 3) >= 2) {
                    int q   = tid + j * 256;
                    int dst = q + ((q >> 10) << 1);
                    cp16(h_s_u32 + dst * 16, srcb + (q >> 3) * 64 + (q & 7) * 4);
                }
            }
            cp_commit();
        }

        // Z gates (kc==0 lanes), issued early to hide DRAM latency
        float zv[16];
        if (kc == 0) {
            const float* zb = g_Z + ((size_t)s * BATCH + gb0) * GATES + uu;
#pragma unroll
            for (int bi = 0; bi < 4; ++bi) {
                const float* z = zb + (size_t)bi * GATES;
                zv[bi * 4 + 0] = __ldcg(z);
                zv[bi * 4 + 1] = __ldcg(z + 512);
                zv[bi * 4 + 2] = __ldcg(z + 1024);
                zv[bi * 4 + 3] = __ldcg(z + 1536);
            }
        }

        cp_wait1();          // phase A landed
        __syncthreads();

        unsigned long long aif[4] = {0, 0, 0, 0};
        unsigned long long ago[4] = {0, 0, 0, 0};

        if (s > 0) {
            // compute phase A (i = 0..63) while phase B streams in
#pragma unroll 8
            for (int i = 0; i < 64; ++i) {
                ulonglong2 w  = wp[i * 8];
                float4     hv = hp[i * 8];
                unsigned long long p;
                p = pack2(hv.x); aif[0] = fma2(p, w.x, aif[0]); ago[0] = fma2(p, w.y, ago[0]);
                p = pack2(hv.y); aif[1] = fma2(p, w.x, aif[1]); ago[1] = fma2(p, w.y, ago[1]);
                p = pack2(hv.z); aif[2] = fma2(p, w.x, aif[2]); ago[2] = fma2(p, w.y, ago[2]);
                p = pack2(hv.w); aif[3] = fma2(p, w.x, aif[3]); ago[3] = fma2(p, w.y, ago[3]);
            }
        }

        cp_wait0();          // phase B landed
        __syncthreads();

        if (s > 0) {
#pragma unroll 8
            for (int i = 64; i < 128; ++i) {
                ulonglong2 w  = wp[i * 8];
                float4     hv = hp[i * 8];
                unsigned long long p;
                p = pack2(hv.x); aif[0] = fma2(p, w.x, aif[0]); ago[0] = fma2(p, w.y, ago[0]);
                p = pack2(hv.y); aif[1] = fma2(p, w.x, aif[1]); ago[1] = fma2(p, w.y, ago[1]);
                p = pack2(hv.z); aif[2] = fma2(p, w.x, aif[2]); ago[2] = fma2(p, w.y, ago[2]);
                p = pack2(hv.w); aif[3] = fma2(p, w.x, aif[3]); ago[3] = fma2(p, w.y, ago[3]);
            }
        }

        // ---- butterfly reduce over kc (lane bits 0..1) ----
        float fi[4], ff[4], fg_[4], fo[4];
#pragma unroll
        for (int bi = 0; bi < 4; ++bi) {
            fi[bi]  = lo2(aif[bi]); ff[bi] = hi2(aif[bi]);
            fg_[bi] = lo2(ago[bi]); fo[bi] = hi2(ago[bi]);
        }
#pragma unroll
        for (int d = 1; d <= 2; d <<= 1) {
#pragma unroll
            for (int bi = 0; bi < 4; ++bi) {
                fi[bi]  += __shfl_xor_sync(0xffffffffu, fi[bi],  d);
                ff[bi]  += __shfl_xor_sync(0xffffffffu, ff[bi],  d);
                fg_[bi] += __shfl_xor_sync(0xffffffffu, fg_[bi], d);
                fo[bi]  += __shfl_xor_sync(0xffffffffu, fo[bi],  d);
            }
        }

        if (kc == 0) {
            float hv[4];
#pragma unroll
            for (int bi = 0; bi < 4; ++bi) {
                float ai = zv[bi * 4 + 0] + fi[bi];
                float af = zv[bi * 4 + 1] + ff[bi];
                float ag = zv[bi * 4 + 2] + fg_[bi];
                float ao = zv[bi * 4 + 3] + fo[bi];
                float ig  = sigmoidf_(ai);
                float fg2 = sigmoidf_(af);
                float gg  = tanhf(ag);
                float og  = sigmoidf_(ao);
                c[bi] = fg2 * c[bi] + ig * gg;
                hv[bi] = og * tanhf(c[bi]);
            }
            *(float4*)(g_hT[(s + 1) & 1] + uu * 64 + gb0) =
                make_float4(hv[0], hv[1], hv[2], hv[3]);
            __threadfence();
        }

        grid_barrier(sense);
    }
}

// ---------------- kernels 3/4: y = tanh(x @ W + bias), 64x512 --------------
template<int SK, int SB>
__global__ void __launch_bounds__(256)
fc_tanh_kernel(const float* __restrict__ x, const float* __restrict__ W,
               const float* __restrict__ bias, float* __restrict__ y)
{
    int o = blockIdx.x * blockDim.x + threadIdx.x;
    int b = o >> 9, j = o & 511;
    const float* xp = x + b * SB;
    float a0 = 0.f, a1 = 0.f, a2 = 0.f, a3 = 0.f;
#pragma unroll 4
    for (int k = 0; k < HID; k += 4) {
        a0 += xp[(k + 0) * SK] * W[(size_t)(k + 0) * HID + j];
        a1 += xp[(k + 1) * SK] * W[(size_t)(k + 1) * HID + j];
        a2 += xp[(k + 2) * SK] * W[(size_t)(k + 2) * HID + j];
        a3 += xp[(k + 3) * SK] * W[(size_t)(k + 3) * HID + j];
    }
    y[o] = tanhf((a0 + a1) + (a2 + a3) + bias[j]);
}

// ---------------- kernel 5: logits = y2 @ W3 + b3 ----------------
__global__ void __launch_bounds__(128)
logits_kernel(const float* __restrict__ y, const float* __restrict__ W3,
              const float* __restrict__ b3, float* __restrict__ out)
{
    __shared__ float ys[128][68];
    const int j = blockIdx.x * 128 + threadIdx.x;

    float acc[64];
#pragma unroll
    for (int b = 0; b < 64; ++b) acc[b] = 0.0f;

    for (int kc = 0; kc < HID; kc += 128) {
        __syncthreads();
        for (int q = threadIdx.x; q < 128 * 64; q += 128) {
            int b = q >> 7, k = q & 127;
            ys[k][b] = y[b * HID + kc + k];
        }
        __syncthreads();
        if (j < VOCAB) {
#pragma unroll 4
            for (int k = 0; k < 128; ++k) {
                float w = W3[(size_t)(kc + k) * VOCAB + j];
                const float4* yr = (const float4*)&ys[k][0];
#pragma unroll
                for (int b4 = 0; b4 < 16; ++b4) {
                    float4 v = yr[b4];
                    acc[b4 * 4 + 0] += v.x * w;
                    acc[b4 * 4 + 1] += v.y * w;
                    acc[b4 * 4 + 2] += v.z * w;
                    acc[b4 * 4 + 3] += v.w * w;
                }
            }
        }
    }
    if (j < VOCAB) {
        float bb = b3[j];
#pragma unroll
        for (int b = 0; b < 64; ++b)
            out[(size_t)b * VOCAB + j] = acc[b] + bb;
    }
}

// ---------------- kernel 6: row-wise log_softmax ----------------
__global__ void __launch_bounds__(1024)
logsoftmax_kernel(const float* __restrict__ logits, float* __restrict__ out)
{
    __shared__ float red[32];
    const int b = blockIdx.x;
    const float* row  = logits + (size_t)b * VOCAB;
    float*       orow = out    + (size_t)b * VOCAB;
    const int tid = threadIdx.x;

    float m = -1e30f;
    for (int j = tid; j < VOCAB; j += 1024) m = fmaxf(m, row[j]);
#pragma unroll
    for (int o = 16; o; o >>= 1) m = fmaxf(m, __shfl_xor_sync(0xffffffffu, m, o));
    if ((tid & 31) == 0) red[tid >> 5] = m;
    __syncthreads();
    if (tid < 32) {
        float v = red[tid];
#pragma unroll
        for (int o = 16; o; o >>= 1) v = fmaxf(v, __shfl_xor_sync(0xffffffffu, v, o));
        red[tid] = v;
    }
    __syncthreads();
    m = red[0];

    float sum = 0.0f;
    for (int j = tid; j < VOCAB; j += 1024) sum += __expf(row[j] - m);
#pragma unroll
    for (int o = 16; o; o >>= 1) sum += __shfl_xor_sync(0xffffffffu, sum, o);
    __syncthreads();
    if ((tid & 31) == 0) red[tid >> 5] = sum;
    __syncthreads();
    if (tid < 32) {
        float v = red[tid];
#pragma unroll
        for (int o = 16; o; o >>= 1) v += __shfl_xor_sync(0xffffffffu, v, o);
        red[tid] = v;
    }
    __syncthreads();
    float lse = m + logf(red[0]);

    for (int j = tid; j < VOCAB; j += 1024) orow[j] = row[j] - lse;
}

// ---------------- launch ----------------
extern "C" void kernel_launch(void* const* d_in, const int* in_sizes, int n_in,
                              void* d_out, int out_size)
{
    const int*   inputs = (const int*)  d_in[0];
    const float* emb    = (const float*)d_in[1];
    const float* Wi     = (const float*)d_in[2];
    const float* Wh     = (const float*)d_in[3];
    const float* bvec   = (const float*)d_in[4];
    const float* W1     = (const float*)d_in[5];
    const float* b1     = (const float*)d_in[6];
    const float* W2     = (const float*)d_in[7];
    const float* b2     = (const float*)d_in[8];
    const float* W3     = (const float*)d_in[9];
    const float* b3     = (const float*)d_in[10];
    float* out = (float*)d_out;

    void *p_h = 0, *p_y1 = 0, *p_y2 = 0, *p_lg = 0;
    cudaGetSymbolAddress(&p_h,  g_hT);     // final h in g_hT[0], k-major [u][b]
    cudaGetSymbolAddress(&p_y1, g_y1);
    cudaGetSymbolAddress(&p_y2, g_y2);
    cudaGetSymbolAddress(&p_lg, g_logits);

    // 1. Z = emb[inputs] @ Wi + b  (time-parallel)
    embed_gemm_kernel<<<dim3(GATES / 128, (SEQ * BATCH) / 128), 256>>>(inputs, emb, Wi, bvec);

    // 2. persistent LSTM recurrence
    cudaFuncSetAttribute(lstm_kernel, cudaFuncAttributeMaxDynamicSharedMemorySize, LSTM_SMEM);
    lstm_kernel<<<NBLK, 256, LSTM_SMEM>>>(Wh);

    // 3/4. dense tanh layers (fc1 reads k-major h)
    fc_tanh_kernel<64, 1><<<128, 256>>>((const float*)p_h,  W1, b1, (float*)p_y1);
    fc_tanh_kernel<1, 512><<<128, 256>>>((const float*)p_y1, W2, b2, (float*)p_y2);

    // 5. vocab projection
    logits_kernel<<<(VOCAB + 127) / 128, 128>>>((const float*)p_y2, W3, b3, (float*)p_lg);

    // 6. log_softmax
    logsoftmax_kernel<<<BATCH, 1024>>>((const float*)p_lg, out);
}

// round 6
// speedup vs baseline: 1.7108x; 1.0584x over previous
#include <cuda_runtime.h>
#include <math.h>

// ---------------- problem constants ----------------
#define BATCH   64
#define SEQ     512
#define EMB     256
#define HID     512
#define GATES   2048           // 4*HID
#define VOCAB   50257
#define NBLK    128            // persistent LSTM grid (<=148 SMs, 1 block/SM)

// ---------------- device scratch (static, no allocs) ----------------
__device__ float g_Z[(size_t)SEQ * BATCH * GATES];   // 256 MB: x@Wi + b, [s][b][4H]
__device__ float g_hT[2][HID * BATCH];               // hidden state, k-major [u][b]
__device__ float g_y1[BATCH * HID];
__device__ float g_y2[BATCH * HID];
__device__ float g_logits[(size_t)BATCH * VOCAB];
__device__ unsigned g_bar_cnt   = 0;
__device__ unsigned g_bar_sense = 0;

// ---------------- packed f32x2 helpers (FFMA2 path, sm_100+) --------------
__device__ __forceinline__ unsigned long long fma2(unsigned long long a,
                                                   unsigned long long b,
                                                   unsigned long long c)
{
    unsigned long long d;
    asm("fma.rn.f32x2 %0, %1, %2, %3;" : "=l"(d) : "l"(a), "l"(b), "l"(c));
    return d;
}
__device__ __forceinline__ unsigned long long pack2(float x)
{
    unsigned long long d;
    unsigned u = __float_as_uint(x);
    asm("mov.b64 %0, {%1, %1};" : "=l"(d) : "r"(u));
    return d;
}
__device__ __forceinline__ float lo2(unsigned long long v) { return __uint_as_float((unsigned)v); }
__device__ __forceinline__ float hi2(unsigned long long v) { return __uint_as_float((unsigned)(v >> 32)); }

// ---------------- fast activations (MUFU.TANH) ----------------
__device__ __forceinline__ float tanh_fast(float x)
{
    float y;
    asm("tanh.approx.f32 %0, %1;" : "=f"(y) : "f"(x));
    return y;
}
__device__ __forceinline__ float sigmoid_fast(float x)
{
    return 0.5f * tanh_fast(0.5f * x) + 0.5f;
}

// ---------------- cp.async helpers ----------------
__device__ __forceinline__ void cp16(unsigned dst_u32, const void* src)
{
    asm volatile("cp.async.cg.shared.global [%0], [%1], 16;"
                 :: "r"(dst_u32), "l"(src) : "memory");
}
__device__ __forceinline__ void cp_commit()
{
    asm volatile("cp.async.commit_group;" ::: "memory");
}
__device__ __forceinline__ void cp_wait1()
{
    asm volatile("cp.async.wait_group 1;" ::: "memory");
}
__device__ __forceinline__ void cp_wait0()
{
    asm volatile("cp.async.wait_group 0;" ::: "memory");
}

// ---------------- grid barrier: release/acquire, single poller ------------
__device__ __forceinline__ void grid_barrier(unsigned &sense)
{
    __syncthreads();
    if (threadIdx.x == 0) {
        sense ^= 1u;
        unsigned old;
        asm volatile("atom.add.release.gpu.global.u32 %0, [%1], %2;"
                     : "=r"(old) : "l"(&g_bar_cnt), "r"(1u) : "memory");
        if (old == NBLK - 1u) {
            asm volatile("st.global.relaxed.gpu.u32 [%0], %1;"
                         :: "l"(&g_bar_cnt), "r"(0u) : "memory");
            asm volatile("st.global.release.gpu.u32 [%0], %1;"
                         :: "l"(&g_bar_sense), "r"(sense) : "memory");
        } else {
            unsigned v;
            do {
                asm volatile("ld.global.acquire.gpu.u32 %0, [%1];"
                             : "=r"(v) : "l"(&g_bar_sense) : "memory");
            } while (v != sense);
        }
    }
    __syncthreads();
}

// ---------------- kernel 1: Z = gather(emb, inputs) @ Wi + b --------------
// (R2-proven, unchanged) 128x128 tile, K-chunks of 16, 8x8 thread tile, f32x2.
__global__ void __launch_bounds__(256, 2)
embed_gemm_kernel(const int* __restrict__ inputs, const float* __restrict__ emb,
                  const float* __restrict__ Wi, const float* __restrict__ bias)
{
    __shared__ float As[128][17];
    __shared__ float Bs[16][132];

    const int t  = threadIdx.x;
    const int mt = blockIdx.y;
    const int nt = blockIdx.x;
    const int tx = t & 15;
    const int ty = t >> 4;

    const int ra   = t >> 1;
    const int koff = (t & 1) * 8;
    const int rowg = mt * 128 + ra;
    const int s    = rowg >> 6;
    const int b    = rowg & 63;
    const float* erow = emb + (size_t)inputs[b * SEQ + s] * EMB;

    const int bkr  = t >> 4;
    const int bcol = (t & 15) * 8;

    unsigned long long acc[8][4];
#pragma unroll
    for (int i = 0; i < 8; ++i)
#pragma unroll
        for (int j = 0; j < 4; ++j) acc[i][j] = 0ULL;

    for (int k0 = 0; k0 < EMB; k0 += 16) {
        {
            float4 a0 = *(const float4*)(erow + k0 + koff);
            float4 a1 = *(const float4*)(erow + k0 + koff + 4);
            As[ra][koff + 0] = a0.x; As[ra][koff + 1] = a0.y;
            As[ra][koff + 2] = a0.z; As[ra][koff + 3] = a0.w;
            As[ra][koff + 4] = a1.x; As[ra][koff + 5] = a1.y;
            As[ra][koff + 6] = a1.z; As[ra][koff + 7] = a1.w;
        }
        {
            const float* wsrc = Wi + (size_t)(k0 + bkr) * GATES + nt * 128 + bcol;
            float4 b0v = *(const float4*)(wsrc);
            float4 b1v = *(const float4*)(wsrc + 4);
            *(float4*)&Bs[bkr][bcol]     = b0v;
            *(float4*)&Bs[bkr][bcol + 4] = b1v;
        }
        __syncthreads();

#pragma unroll
        for (int k = 0; k < 16; ++k) {
            unsigned long long pa[8];
#pragma unroll
            for (int i = 0; i < 4; ++i) {
                pa[i]     = pack2(As[ty * 4 + i][k]);
                pa[i + 4] = pack2(As[64 + ty * 4 + i][k]);
            }
            ulonglong2 b0v = *(const ulonglong2*)&Bs[k][tx * 4];
            ulonglong2 b1v = *(const ulonglong2*)&Bs[k][64 + tx * 4];
#pragma unroll
            for (int i = 0; i < 8; ++i) {
                acc[i][0] = fma2(pa[i], b0v.x, acc[i][0]);
                acc[i][1] = fma2(pa[i], b0v.y, acc[i][1]);
                acc[i][2] = fma2(pa[i], b1v.x, acc[i][2]);
                acc[i][3] = fma2(pa[i], b1v.y, acc[i][3]);
            }
        }
        __syncthreads();
    }

    float4 bb0 = *(const float4*)(bias + nt * 128 + tx * 4);
    float4 bb1 = *(const float4*)(bias + nt * 128 + 64 + tx * 4);
#pragma unroll
    for (int i = 0; i < 8; ++i) {
        int row = mt * 128 + ((i < 4) ? (ty * 4 + i) : (64 + ty * 4 + i - 4));
        float* zr = g_Z + (size_t)row * GATES + nt * 128;
        float4 v0, v1;
        v0.x = lo2(acc[i][0]) + bb0.x; v0.y = hi2(acc[i][0]) + bb0.y;
        v0.z = lo2(acc[i][1]) + bb0.z; v0.w = hi2(acc[i][1]) + bb0.w;
        v1.x = lo2(acc[i][2]) + bb1.x; v1.y = hi2(acc[i][2]) + bb1.y;
        v1.z = lo2(acc[i][3]) + bb1.z; v1.w = hi2(acc[i][3]) + bb1.w;
        *(float4*)(zr + tx * 4)      = v0;
        *(float4*)(zr + 64 + tx * 4) = v1;
    }
}

// ---------------- kernel 2: persistent LSTM over 512 steps ----------------
// 128 blocks = 64 unit-groups x 2 batch-halves; block = 8 units x 32 batches.
// 512 threads (16 warps -> 4 warps/SMSP for latency hiding), k-split 8.
// tid bits: [0:3)=kc, [3)=u0, [4)=bg0, [5:7)=u_hi, [7:9)=bg_hi.
// Thread: 1 unit, 4 batches, K-strip of 64 -> 512 fma2/step.
// smem: h_s4 / Whs, both [4103] 16B elems, skew = +kc elem per strip.
#define LSTM_SMEM (65648 * 2)

__global__ void __launch_bounds__(512, 1)
lstm_kernel(const float* __restrict__ Wh)
{
    extern __shared__ float sm[];
    float4*     h_s4 = (float4*)sm;
    ulonglong2* Whs  = (ulonglong2*)((char*)sm + 65648);

    const int tid = threadIdx.x;
    const int kc  = tid & 7;
    const int u   = (((tid >> 5) & 3) << 1) | ((tid >> 3) & 1);   // 0..7
    const int bg  = (((tid >> 7) & 3) << 1) | ((tid >> 4) & 1);   // 0..7
    const int ub  = blockIdx.x >> 1;        // unit group 0..63
    const int bh  = blockIdx.x & 1;         // batch half
    const int uu  = ub * 8 + u;             // global unit
    const int gb0 = bh * 32 + bg * 4;       // first of this thread's 4 batches

    const unsigned h_s_u32 = (unsigned)__cvta_generic_to_shared(h_s4);

    // stage Wh slice once: unskewed idx i = k*8+u2, skew +(i>>9)
    for (int i = tid; i < HID * 8; i += 512) {
        int k = i >> 3, u2 = i & 7;
        const float* w = Wh + (size_t)k * GATES + ub * 8 + u2;
        float4 v = make_float4(w[0], w[512], w[1024], w[1536]);
        Whs[i + (i >> 9)] = *(ulonglong2*)&v;
    }

    float c = 0.0f;            // cell state: lanes kc<4 own batch gb0+kc
    unsigned sense = 0;
    __syncthreads();

    const ulonglong2* wp = Whs  + kc * 513 + u;    // element i: wp[i*8]
    const float4*     hp = h_s4 + kc * 513 + bg;   // element i: hp[i*8]

    // staging ownership: lk = tid>>3 (strip-local k), cc = tid&7 (batch grp)
    const int lk = tid >> 3;
    const int cc = tid & 7;

    // prefetch Z for step 0 (lanes kc<4: batch gb0+kc, 4 gates)
    float zi = 0.f, zf = 0.f, zg = 0.f, zo = 0.f;
    if (kc < 4) {
        const float* z = g_Z + (size_t)(gb0 + kc) * GATES + uu;
        zi = __ldcg(z);        zf = __ldcg(z + 512);
        zg = __ldcg(z + 1024); zo = __ldcg(z + 1536);
    }

    for (int s = 0; s < SEQ; ++s) {
        // ---- two-phase cp.async staging of h_{s-1} ----
        if (s > 0) {
            const float4* src4 = (const float4*)g_hT[s & 1];
            // phase A: strip-local k < 32  (threads with lk<32 own all 8 strips)
            if (lk < 32) {
#pragma unroll
                for (int j = 0; j < 8; ++j) {
                    int dst = tid + j * 513;                  // q + kc skew
                    const float4* sp = src4 + (j * 64 + lk) * 16 + bh * 8 + cc;
                    cp16(h_s_u32 + dst * 16, sp);
                }
            }
            cp_commit();
            if (lk >= 32) {
#pragma unroll
                for (int j = 0; j < 8; ++j) {
                    int dst = tid + j * 513;
                    const float4* sp = src4 + (j * 64 + lk) * 16 + bh * 8 + cc;
                    cp16(h_s_u32 + dst * 16, sp);
                }
            }
            cp_commit();
        }

        unsigned long long aif[4] = {0, 0, 0, 0};
        unsigned long long ago[4] = {0, 0, 0, 0};

        if (s > 0) {
            cp_wait1();          // phase A landed (this thread's group 0)
            __syncthreads();

#pragma unroll 8
            for (int i = 0; i < 32; ++i) {
                ulonglong2 w  = wp[i * 8];
                float4     hv = hp[i * 8];
                unsigned long long p;
                p = pack2(hv.x); aif[0] = fma2(p, w.x, aif[0]); ago[0] = fma2(p, w.y, ago[0]);
                p = pack2(hv.y); aif[1] = fma2(p, w.x, aif[1]); ago[1] = fma2(p, w.y, ago[1]);
                p = pack2(hv.z); aif[2] = fma2(p, w.x, aif[2]); ago[2] = fma2(p, w.y, ago[2]);
                p = pack2(hv.w); aif[3] = fma2(p, w.x, aif[3]); ago[3] = fma2(p, w.y, ago[3]);
            }

            cp_wait0();          // phase B landed
            __syncthreads();

#pragma unroll 8
            for (int i = 32; i < 64; ++i) {
                ulonglong2 w  = wp[i * 8];
                float4     hv = hp[i * 8];
                unsigned long long p;
                p = pack2(hv.x); aif[0] = fma2(p, w.x, aif[0]); ago[0] = fma2(p, w.y, ago[0]);
                p = pack2(hv.y); aif[1] = fma2(p, w.x, aif[1]); ago[1] = fma2(p, w.y, ago[1]);
                p = pack2(hv.z); aif[2] = fma2(p, w.x, aif[2]); ago[2] = fma2(p, w.y, ago[2]);
                p = pack2(hv.w); aif[3] = fma2(p, w.x, aif[3]); ago[3] = fma2(p, w.y, ago[3]);
            }
        }

        // ---- butterfly reduce over kc (lane bits 0..2) ----
        float fi[4], ff[4], fg_[4], fo[4];
#pragma unroll
        for (int bi = 0; bi < 4; ++bi) {
            fi[bi]  = lo2(aif[bi]); ff[bi] = hi2(aif[bi]);
            fg_[bi] = lo2(ago[bi]); fo[bi] = hi2(ago[bi]);
        }
#pragma unroll
        for (int d = 1; d <= 4; d <<= 1) {
#pragma unroll
            for (int bi = 0; bi < 4; ++bi) {
                fi[bi]  += __shfl_xor_sync(0xffffffffu, fi[bi],  d);
                ff[bi]  += __shfl_xor_sync(0xffffffffu, ff[bi],  d);
                fg_[bi] += __shfl_xor_sync(0xffffffffu, fg_[bi], d);
                fo[bi]  += __shfl_xor_sync(0xffffffffu, fo[bi],  d);
            }
        }

        // ---- epilogue: lane kc=e handles batch gb0+e (4 MUFU.TANH) ----
        if (kc < 4) {
            float ai = zi + fi[kc];
            float af = zf + ff[kc];
            float ag = zg + fg_[kc];
            float ao = zo + fo[kc];
            float ig  = sigmoid_fast(ai);
            float fg2 = sigmoid_fast(af);
            float gg  = tanh_fast(ag);
            float og  = sigmoid_fast(ao);
            c = fg2 * c + ig * gg;
            float hv = og * tanh_fast(c);
            g_hT[(s + 1) & 1][uu * 64 + gb0 + kc] = hv;   // final h in g_hT[0]
        }

        // ---- prefetch Z for step s+1 (hides DRAM latency behind barrier) --
        if (kc < 4 && s + 1 < SEQ) {
            const float* z = g_Z + ((size_t)(s + 1) * BATCH + gb0 + kc) * GATES + uu;
            zi = __ldcg(z);        zf = __ldcg(z + 512);
            zg = __ldcg(z + 1024); zo = __ldcg(z + 1536);
        }

        grid_barrier(sense);
    }
}

// ---------------- kernels 3/4: y = tanh(x @ W + bias), 64x512 --------------
template<int SK, int SB>
__global__ void __launch_bounds__(256)
fc_tanh_kernel(const float* __restrict__ x, const float* __restrict__ W,
               const float* __restrict__ bias, float* __restrict__ y)
{
    int o = blockIdx.x * blockDim.x + threadIdx.x;
    int b = o >> 9, j = o & 511;
    const float* xp = x + b * SB;
    float a0 = 0.f, a1 = 0.f, a2 = 0.f, a3 = 0.f;
#pragma unroll 4
    for (int k = 0; k < HID; k += 4) {
        a0 += xp[(k + 0) * SK] * W[(size_t)(k + 0) * HID + j];
        a1 += xp[(k + 1) * SK] * W[(size_t)(k + 1) * HID + j];
        a2 += xp[(k + 2) * SK] * W[(size_t)(k + 2) * HID + j];
        a3 += xp[(k + 3) * SK] * W[(size_t)(k + 3) * HID + j];
    }
    y[o] = tanhf((a0 + a1) + (a2 + a3) + bias[j]);
}

// ---------------- kernel 5: logits = y2 @ W3 + b3 ----------------
__global__ void __launch_bounds__(128)
logits_kernel(const float* __restrict__ y, const float* __restrict__ W3,
              const float* __restrict__ b3, float* __restrict__ out)
{
    __shared__ float ys[128][68];
    const int j = blockIdx.x * 128 + threadIdx.x;

    float acc[64];
#pragma unroll
    for (int b = 0; b < 64; ++b) acc[b] = 0.0f;

    for (int kc = 0; kc < HID; kc += 128) {
        __syncthreads();
        for (int q = threadIdx.x; q < 128 * 64; q += 128) {
            int b = q >> 7, k = q & 127;
            ys[k][b] = y[b * HID + kc + k];
        }
        __syncthreads();
        if (j < VOCAB) {
#pragma unroll 4
            for (int k = 0; k < 128; ++k) {
                float w = W3[(size_t)(kc + k) * VOCAB + j];
                const float4* yr = (const float4*)&ys[k][0];
#pragma unroll
                for (int b4 = 0; b4 < 16; ++b4) {
                    float4 v = yr[b4];
                    acc[b4 * 4 + 0] += v.x * w;
                    acc[b4 * 4 + 1] += v.y * w;
                    acc[b4 * 4 + 2] += v.z * w;
                    acc[b4 * 4 + 3] += v.w * w;
                }
            }
        }
    }
    if (j < VOCAB) {
        float bb = b3[j];
#pragma unroll
        for (int b = 0; b < 64; ++b)
            out[(size_t)b * VOCAB + j] = acc[b] + bb;
    }
}

// ---------------- kernel 6: row-wise log_softmax ----------------
__global__ void __launch_bounds__(1024)
logsoftmax_kernel(const float* __restrict__ logits, float* __restrict__ out)
{
    __shared__ float red[32];
    const int b = blockIdx.x;
    const float* row  = logits + (size_t)b * VOCAB;
    float*       orow = out    + (size_t)b * VOCAB;
    const int tid = threadIdx.x;

    float m = -1e30f;
    for (int j = tid; j < VOCAB; j += 1024) m = fmaxf(m, row[j]);
#pragma unroll
    for (int o = 16; o; o >>= 1) m = fmaxf(m, __shfl_xor_sync(0xffffffffu, m, o));
    if ((tid & 31) == 0) red[tid >> 5] = m;
    __syncthreads();
    if (tid < 32) {
        float v = red[tid];
#pragma unroll
        for (int o = 16; o; o >>= 1) v = fmaxf(v, __shfl_xor_sync(0xffffffffu, v, o));
        red[tid] = v;
    }
    __syncthreads();
    m = red[0];

    float sum = 0.0f;
    for (int j = tid; j < VOCAB; j += 1024) sum += __expf(row[j] - m);
#pragma unroll
    for (int o = 16; o; o >>= 1) sum += __shfl_xor_sync(0xffffffffu, sum, o);
    __syncthreads();
    if ((tid & 31) == 0) red[tid >> 5] = sum;
    __syncthreads();
    if (tid < 32) {
        float v = red[tid];
#pragma unroll
        for (int o = 16; o; o >>= 1) v += __shfl_xor_sync(0xffffffffu, v, o);
        red[tid] = v;
    }
    __syncthreads();
    float lse = m + logf(red[0]);

    for (int j = tid; j < VOCAB; j += 1024) orow[j] = row[j] - lse;
}

// ---------------- launch ----------------
extern "C" void kernel_launch(void* const* d_in, const int* in_sizes, int n_in,
                              void* d_out, int out_size)
{
    const int*   inputs = (const int*)  d_in[0];
    const float* emb    = (const float*)d_in[1];
    const float* Wi     = (const float*)d_in[2];
    const float* Wh     = (const float*)d_in[3];
    const float* bvec   = (const float*)d_in[4];
    const float* W1     = (const float*)d_in[5];
    const float* b1     = (const float*)d_in[6];
    const float* W2     = (const float*)d_in[7];
    const float* b2     = (const float*)d_in[8];
    const float* W3     = (const float*)d_in[9];
    const float* b3     = (const float*)d_in[10];
    float* out = (float*)d_out;

    void *p_h = 0, *p_y1 = 0, *p_y2 = 0, *p_lg = 0;
    cudaGetSymbolAddress(&p_h,  g_hT);     // final h in g_hT[0], k-major [u][b]
    cudaGetSymbolAddress(&p_y1, g_y1);
    cudaGetSymbolAddress(&p_y2, g_y2);
    cudaGetSymbolAddress(&p_lg, g_logits);

    // 1. Z = emb[inputs] @ Wi + b  (time-parallel)
    embed_gemm_kernel<<<dim3(GATES / 128, (SEQ * BATCH) / 128), 256>>>(inputs, emb, Wi, bvec);

    // 2. persistent LSTM recurrence
    cudaFuncSetAttribute(lstm_kernel, cudaFuncAttributeMaxDynamicSharedMemorySize, LSTM_SMEM);
    lstm_kernel<<<NBLK, 512, LSTM_SMEM>>>(Wh);

    // 3/4. dense tanh layers (fc1 reads k-major h)
    fc_tanh_kernel<64, 1><<<128, 256>>>((const float*)p_h,  W1, b1, (float*)p_y1);
    fc_tanh_kernel<1, 512><<<128, 256>>>((const float*)p_y1, W2, b2, (float*)p_y2);

    // 5. vocab projection
    logits_kernel<<<(VOCAB + 127) / 128, 128>>>((const float*)p_y2, W3, b3, (float*)p_lg);

    // 6. log_softmax
    logsoftmax_kernel<<<BATCH, 1024>>>((const float*)p_lg, out);
}

// round 7
// speedup vs baseline: 2.0406x; 1.1927x over previous
#include <cuda_runtime.h>
#include <math.h>

// ---------------- problem constants ----------------
#define BATCH   64
#define SEQ     512
#define EMB     256
#define HID     512
#define GATES   2048           // 4*HID
#define VOCAB   50257
#define NBLK    128            // persistent LSTM grid (<=148 SMs, 1 block/SM)

// ---------------- device scratch (static, no allocs) ----------------
__device__ float g_Z[(size_t)SEQ * BATCH * GATES];   // 256 MB: x@Wi + b, [s][b][4H]
__device__ float g_hT[2][HID * BATCH];               // hidden state, k-major [u][b]
__device__ float g_y1[BATCH * HID];
__device__ float g_y2[BATCH * HID];
__device__ float g_logits[(size_t)BATCH * VOCAB];
__device__ unsigned g_bar_cnt   = 0;
__device__ unsigned g_bar_sense = 0;

// ---------------- packed f32x2 helpers (FFMA2 path, sm_100+) --------------
__device__ __forceinline__ unsigned long long fma2(unsigned long long a,
                                                   unsigned long long b,
                                                   unsigned long long c)
{
    unsigned long long d;
    asm("fma.rn.f32x2 %0, %1, %2, %3;" : "=l"(d) : "l"(a), "l"(b), "l"(c));
    return d;
}
__device__ __forceinline__ unsigned long long pack2(float x)
{
    unsigned long long d;
    unsigned u = __float_as_uint(x);
    asm("mov.b64 %0, {%1, %1};" : "=l"(d) : "r"(u));
    return d;
}
__device__ __forceinline__ float lo2(unsigned long long v) { return __uint_as_float((unsigned)v); }
__device__ __forceinline__ float hi2(unsigned long long v) { return __uint_as_float((unsigned)(v >> 32)); }

// ---------------- fast activations (MUFU.TANH) ----------------
__device__ __forceinline__ float tanh_fast(float x)
{
    float y;
    asm("tanh.approx.f32 %0, %1;" : "=f"(y) : "f"(x));
    return y;
}
__device__ __forceinline__ float sigmoid_fast(float x)
{
    return 0.5f * tanh_fast(0.5f * x) + 0.5f;
}

// ---------------- cp.async helpers ----------------
__device__ __forceinline__ void cp16(unsigned dst_u32, const void* src)
{
    asm volatile("cp.async.cg.shared.global [%0], [%1], 16;"
                 :: "r"(dst_u32), "l"(src) : "memory");
}
__device__ __forceinline__ void cp_commit()
{
    asm volatile("cp.async.commit_group;" ::: "memory");
}
__device__ __forceinline__ void cp_wait0()
{
    asm volatile("cp.async.wait_group 0;" ::: "memory");
}

// ---------------- grid barrier: release/acquire, single poller ------------
__device__ __forceinline__ void grid_barrier(unsigned &sense)
{
    __syncthreads();
    if (threadIdx.x == 0) {
        sense ^= 1u;
        unsigned old;
        asm volatile("atom.add.release.gpu.global.u32 %0, [%1], %2;"
                     : "=r"(old) : "l"(&g_bar_cnt), "r"(1u) : "memory");
        if (old == NBLK - 1u) {
            asm volatile("st.global.relaxed.gpu.u32 [%0], %1;"
                         :: "l"(&g_bar_cnt), "r"(0u) : "memory");
            asm volatile("st.global.release.gpu.u32 [%0], %1;"
                         :: "l"(&g_bar_sense), "r"(sense) : "memory");
        } else {
            unsigned v;
            do {
                asm volatile("ld.global.acquire.gpu.u32 %0, [%1];"
                             : "=r"(v) : "l"(&g_bar_sense) : "memory");
            } while (v != sense);
        }
    }
    __syncthreads();
}

// ---------------- kernel 1: Z = gather(emb, inputs) @ Wi + b --------------
// (R2-proven, unchanged) 128x128 tile, K-chunks of 16, 8x8 thread tile, f32x2.
__global__ void __launch_bounds__(256, 2)
embed_gemm_kernel(const int* __restrict__ inputs, const float* __restrict__ emb,
                  const float* __restrict__ Wi, const float* __restrict__ bias)
{
    __shared__ float As[128][17];
    __shared__ float Bs[16][132];

    const int t  = threadIdx.x;
    const int mt = blockIdx.y;
    const int nt = blockIdx.x;
    const int tx = t & 15;
    const int ty = t >> 4;

    const int ra   = t >> 1;
    const int koff = (t & 1) * 8;
    const int rowg = mt * 128 + ra;
    const int s    = rowg >> 6;
    const int b    = rowg & 63;
    const float* erow = emb + (size_t)inputs[b * SEQ + s] * EMB;

    const int bkr  = t >> 4;
    const int bcol = (t & 15) * 8;

    unsigned long long acc[8][4];
#pragma unroll
    for (int i = 0; i < 8; ++i)
#pragma unroll
        for (int j = 0; j < 4; ++j) acc[i][j] = 0ULL;

    for (int k0 = 0; k0 < EMB; k0 += 16) {
        {
            float4 a0 = *(const float4*)(erow + k0 + koff);
            float4 a1 = *(const float4*)(erow + k0 + koff + 4);
            As[ra][koff + 0] = a0.x; As[ra][koff + 1] = a0.y;
            As[ra][koff + 2] = a0.z; As[ra][koff + 3] = a0.w;
            As[ra][koff + 4] = a1.x; As[ra][koff + 5] = a1.y;
            As[ra][koff + 6] = a1.z; As[ra][koff + 7] = a1.w;
        }
        {
            const float* wsrc = Wi + (size_t)(k0 + bkr) * GATES + nt * 128 + bcol;
            float4 b0v = *(const float4*)(wsrc);
            float4 b1v = *(const float4*)(wsrc + 4);
            *(float4*)&Bs[bkr][bcol]     = b0v;
            *(float4*)&Bs[bkr][bcol + 4] = b1v;
        }
        __syncthreads();

#pragma unroll
        for (int k = 0; k < 16; ++k) {
            unsigned long long pa[8];
#pragma unroll
            for (int i = 0; i < 4; ++i) {
                pa[i]     = pack2(As[ty * 4 + i][k]);
                pa[i + 4] = pack2(As[64 + ty * 4 + i][k]);
            }
            ulonglong2 b0v = *(const ulonglong2*)&Bs[k][tx * 4];
            ulonglong2 b1v = *(const ulonglong2*)&Bs[k][64 + tx * 4];
#pragma unroll
            for (int i = 0; i < 8; ++i) {
                acc[i][0] = fma2(pa[i], b0v.x, acc[i][0]);
                acc[i][1] = fma2(pa[i], b0v.y, acc[i][1]);
                acc[i][2] = fma2(pa[i], b1v.x, acc[i][2]);
                acc[i][3] = fma2(pa[i], b1v.y, acc[i][3]);
            }
        }
        __syncthreads();
    }

    float4 bb0 = *(const float4*)(bias + nt * 128 + tx * 4);
    float4 bb1 = *(const float4*)(bias + nt * 128 + 64 + tx * 4);
#pragma unroll
    for (int i = 0; i < 8; ++i) {
        int row = mt * 128 + ((i < 4) ? (ty * 4 + i) : (64 + ty * 4 + i - 4));
        float* zr = g_Z + (size_t)row * GATES + nt * 128;
        float4 v0, v1;
        v0.x = lo2(acc[i][0]) + bb0.x; v0.y = hi2(acc[i][0]) + bb0.y;
        v0.z = lo2(acc[i][1]) + bb0.z; v0.w = hi2(acc[i][1]) + bb0.w;
        v1.x = lo2(acc[i][2]) + bb1.x; v1.y = hi2(acc[i][2]) + bb1.y;
        v1.z = lo2(acc[i][3]) + bb1.z; v1.w = hi2(acc[i][3]) + bb1.w;
        *(float4*)(zr + tx * 4)      = v0;
        *(float4*)(zr + 64 + tx * 4) = v1;
    }
}

// ---------------- kernel 2: persistent LSTM over 512 steps ----------------
// 128 blocks = 64 unit-groups x 2 batch-halves; block = 8 units x 32 batches.
// 256 threads = 8 warps. WARP = one kc strip (k fixed per inner iteration!),
// lanes = (up 0..3) x (bg 0..7). Thread tile = 2 units x 4 batches, 64 k.
// All inner-loop LDS are broadcast rows: w = 64B/instr, h = 128B/instr ->
// conflict-free, ~1 cyc each; crossbar no longer binds (was the R2-R6 wall).
// kc reduction via skewed smem (red[p*9+kc]); epilogue: thread=pair p=tid.
#define LSTM_SMEM (65536 + 65536 + 36864)

__global__ void __launch_bounds__(256, 1)
lstm_kernel(const float* __restrict__ Wh)
{
    extern __shared__ float sm[];
    float4*     h_s4 = (float4*)sm;                           // [512][8] (64KB)
    ulonglong2* Whs  = (ulonglong2*)((char*)sm + 65536);      // [512][8] (64KB)
    ulonglong2* red  = (ulonglong2*)((char*)sm + 131072);     // [256 p][9] skew

    const int tid = threadIdx.x;
    const int kc  = tid >> 5;            // warp id = k-strip 0..7
    const int up  = (tid >> 3) & 3;      // unit pair 0..3 (units 2up, 2up+1)
    const int bg  = tid & 7;             // batch group 0..7 (4 batches)
    const int ub  = blockIdx.x >> 1;     // unit group 0..63
    const int bh  = blockIdx.x & 1;      // batch half
    const unsigned h_s_u32 = (unsigned)__cvta_generic_to_shared(h_s4);

    // epilogue ownership: pair p = tid -> unit eu, local batch ebl
    const int eu  = tid >> 5;            // 0..7
    const int ebl = tid & 31;            // 0..31
    const int euu = ub * 8 + eu;
    const int egb = bh * 32 + ebl;

    // stage Wh slice once: Whs[k*8+u] = {(wi,wf),(wg,wo)} for col = ub*8+u
    for (int i = tid; i < HID * 8; i += 256) {
        int k = i >> 3, u2 = i & 7;
        const float* w = Wh + (size_t)k * GATES + ub * 8 + u2;
        float4 v = make_float4(w[0], w[512], w[1024], w[1536]);
        Whs[i] = *(ulonglong2*)&v;
    }

    float c = 0.0f;                      // cell state of pair p = tid
    unsigned sense = 0;
    __syncthreads();

    const ulonglong2* wp = Whs  + kc * 512 + up * 2;   // iter i: wp[i*8], wp[i*8+1]
    const float4*     hp = h_s4 + kc * 512 + bg;       // iter i: hp[i*8]

    // Z prefetch for step 0 (gates for pair p)
    const float* z0 = g_Z + (size_t)egb * GATES + euu;
    float zi = __ldcg(z0), zf = __ldcg(z0 + 512);
    float zg = __ldcg(z0 + 1024), zo = __ldcg(z0 + 1536);

    for (int s = 0; s < SEQ; ++s) {
        // ---- single-phase cp.async staging of h_{s-1} (64KB, coalesced) ----
        if (s > 0) {
            const float4* src4 = (const float4*)g_hT[s & 1];
#pragma unroll
            for (int j = 0; j < 16; ++j) {
                int chunk = tid + j * 256;                 // 0..4095
                int k = chunk >> 3, bgc = chunk & 7;
                cp16(h_s_u32 + chunk * 16, src4 + k * 16 + bh * 8 + bgc);
            }
            cp_commit();
            cp_wait0();
        }
        __syncthreads();   // h_s ready (and red from prev step fully consumed)

        unsigned long long aif[2][4] = {{0,0,0,0},{0,0,0,0}};
        unsigned long long ago[2][4] = {{0,0,0,0},{0,0,0,0}};

        if (s > 0) {
#pragma unroll 4
            for (int i = 0; i < 64; ++i) {
                ulonglong2 w0 = wp[i * 8];       // unit 2up   (wi,wf),(wg,wo)
                ulonglong2 w1 = wp[i * 8 + 1];   // unit 2up+1
                float4     hv = hp[i * 8];       // 4 batches
                unsigned long long p;
                p = pack2(hv.x);
                aif[0][0] = fma2(p, w0.x, aif[0][0]); ago[0][0] = fma2(p, w0.y, ago[0][0]);
                aif[1][0] = fma2(p, w1.x, aif[1][0]); ago[1][0] = fma2(p, w1.y, ago[1][0]);
                p = pack2(hv.y);
                aif[0][1] = fma2(p, w0.x, aif[0][1]); ago[0][1] = fma2(p, w0.y, ago[0][1]);
                aif[1][1] = fma2(p, w1.x, aif[1][1]); ago[1][1] = fma2(p, w1.y, ago[1][1]);
                p = pack2(hv.z);
                aif[0][2] = fma2(p, w0.x, aif[0][2]); ago[0][2] = fma2(p, w0.y, ago[0][2]);
                aif[1][2] = fma2(p, w1.x, aif[1][2]); ago[1][2] = fma2(p, w1.y, ago[1][2]);
                p = pack2(hv.w);
                aif[0][3] = fma2(p, w0.x, aif[0][3]); ago[0][3] = fma2(p, w0.y, ago[0][3]);
                aif[1][3] = fma2(p, w1.x, aif[1][3]); ago[1][3] = fma2(p, w1.y, ago[1][3]);
            }
        }

        // ---- write partials to skewed red[p*9 + kc] ----
#pragma unroll
        for (int uo = 0; uo < 2; ++uo)
#pragma unroll
            for (int bi = 0; bi < 4; ++bi) {
                int p = (2 * up + uo) * 32 + bg * 4 + bi;
                red[p * 9 + kc] = make_ulonglong2(aif[uo][bi], ago[uo][bi]);
            }
        __syncthreads();

        // ---- reduce 8 kc partials for pair p = tid; epilogue ----
        {
            float fi = zi, ff = zf, fg_ = zg, fo = zo;
#pragma unroll
            for (int k8 = 0; k8 < 8; ++k8) {
                ulonglong2 v = red[tid * 9 + k8];
                fi += lo2(v.x); ff += hi2(v.x);
                fg_ += lo2(v.y); fo += hi2(v.y);
            }
            float ig  = sigmoid_fast(fi);
            float fg2 = sigmoid_fast(ff);
            float gg  = tanh_fast(fg_);
            float og  = sigmoid_fast(fo);
            c = fg2 * c + ig * gg;
            float hv = og * tanh_fast(c);
            g_hT[(s + 1) & 1][euu * 64 + egb] = hv;    // final h in g_hT[0]
        }

        // ---- prefetch Z for step s+1 (hides DRAM latency behind barrier) --
        if (s + 1 < SEQ) {
            const float* z = g_Z + ((size_t)(s + 1) * BATCH + egb) * GATES + euu;
            zi = __ldcg(z);        zf = __ldcg(z + 512);
            zg = __ldcg(z + 1024); zo = __ldcg(z + 1536);
        }

        grid_barrier(sense);
    }
}

// ---------------- kernels 3/4: y = tanh(x @ W + bias), 64x512 --------------
template<int SK, int SB>
__global__ void __launch_bounds__(256)
fc_tanh_kernel(const float* __restrict__ x, const float* __restrict__ W,
               const float* __restrict__ bias, float* __restrict__ y)
{
    int o = blockIdx.x * blockDim.x + threadIdx.x;
    int b = o >> 9, j = o & 511;
    const float* xp = x + b * SB;
    float a0 = 0.f, a1 = 0.f, a2 = 0.f, a3 = 0.f;
#pragma unroll 4
    for (int k = 0; k < HID; k += 4) {
        a0 += xp[(k + 0) * SK] * W[(size_t)(k + 0) * HID + j];
        a1 += xp[(k + 1) * SK] * W[(size_t)(k + 1) * HID + j];
        a2 += xp[(k + 2) * SK] * W[(size_t)(k + 2) * HID + j];
        a3 += xp[(k + 3) * SK] * W[(size_t)(k + 3) * HID + j];
    }
    y[o] = tanhf((a0 + a1) + (a2 + a3) + bias[j]);
}

// ---------------- kernel 5: logits = y2 @ W3 + b3 ----------------
__global__ void __launch_bounds__(128)
logits_kernel(const float* __restrict__ y, const float* __restrict__ W3,
              const float* __restrict__ b3, float* __restrict__ out)
{
    __shared__ float ys[128][68];
    const int j = blockIdx.x * 128 + threadIdx.x;

    float acc[64];
#pragma unroll
    for (int b = 0; b < 64; ++b) acc[b] = 0.0f;

    for (int kc = 0; kc < HID; kc += 128) {
        __syncthreads();
        for (int q = threadIdx.x; q < 128 * 64; q += 128) {
            int b = q >> 7, k = q & 127;
            ys[k][b] = y[b * HID + kc + k];
        }
        __syncthreads();
        if (j < VOCAB) {
#pragma unroll 4
            for (int k = 0; k < 128; ++k) {
                float w = W3[(size_t)(kc + k) * VOCAB + j];
                const float4* yr = (const float4*)&ys[k][0];
#pragma unroll
                for (int b4 = 0; b4 < 16; ++b4) {
                    float4 v = yr[b4];
                    acc[b4 * 4 + 0] += v.x * w;
                    acc[b4 * 4 + 1] += v.y * w;
                    acc[b4 * 4 + 2] += v.z * w;
                    acc[b4 * 4 + 3] += v.w * w;
                }
            }
        }
    }
    if (j < VOCAB) {
        float bb = b3[j];
#pragma unroll
        for (int b = 0; b < 64; ++b)
            out[(size_t)b * VOCAB + j] = acc[b] + bb;
    }
}

// ---------------- kernel 6: row-wise log_softmax ----------------
__global__ void __launch_bounds__(1024)
logsoftmax_kernel(const float* __restrict__ logits, float* __restrict__ out)
{
    __shared__ float red[32];
    const int b = blockIdx.x;
    const float* row  = logits + (size_t)b * VOCAB;
    float*       orow = out    + (size_t)b * VOCAB;
    const int tid = threadIdx.x;

    float m = -1e30f;
    for (int j = tid; j < VOCAB; j += 1024) m = fmaxf(m, row[j]);
#pragma unroll
    for (int o = 16; o; o >>= 1) m = fmaxf(m, __shfl_xor_sync(0xffffffffu, m, o));
    if ((tid & 31) == 0) red[tid >> 5] = m;
    __syncthreads();
    if (tid < 32) {
        float v = red[tid];
#pragma unroll
        for (int o = 16; o; o >>= 1) v = fmaxf(v, __shfl_xor_sync(0xffffffffu, v, o));
        red[tid] = v;
    }
    __syncthreads();
    m = red[0];

    float sum = 0.0f;
    for (int j = tid; j < VOCAB; j += 1024) sum += __expf(row[j] - m);
#pragma unroll
    for (int o = 16; o; o >>= 1) sum += __shfl_xor_sync(0xffffffffu, sum, o);
    __syncthreads();
    if ((tid & 31) == 0) red[tid >> 5] = sum;
    __syncthreads();
    if (tid < 32) {
        float v = red[tid];
#pragma unroll
        for (int o = 16; o; o >>= 1) v += __shfl_xor_sync(0xffffffffu, v, o);
        red[tid] = v;
    }
    __syncthreads();
    float lse = m + logf(red[0]);

    for (int j = tid; j < VOCAB; j += 1024) orow[j] = row[j] - lse;
}

// ---------------- launch ----------------
extern "C" void kernel_launch(void* const* d_in, const int* in_sizes, int n_in,
                              void* d_out, int out_size)
{
    const int*   inputs = (const int*)  d_in[0];
    const float* emb    = (const float*)d_in[1];
    const float* Wi     = (const float*)d_in[2];
    const float* Wh     = (const float*)d_in[3];
    const float* bvec   = (const float*)d_in[4];
    const float* W1     = (const float*)d_in[5];
    const float* b1     = (const float*)d_in[6];
    const float* W2     = (const float*)d_in[7];
    const float* b2     = (const float*)d_in[8];
    const float* W3     = (const float*)d_in[9];
    const float* b3     = (const float*)d_in[10];
    float* out = (float*)d_out;

    void *p_h = 0, *p_y1 = 0, *p_y2 = 0, *p_lg = 0;
    cudaGetSymbolAddress(&p_h,  g_hT);     // final h in g_hT[0], k-major [u][b]
    cudaGetSymbolAddress(&p_y1, g_y1);
    cudaGetSymbolAddress(&p_y2, g_y2);
    cudaGetSymbolAddress(&p_lg, g_logits);

    // 1. Z = emb[inputs] @ Wi + b  (time-parallel)
    embed_gemm_kernel<<<dim3(GATES / 128, (SEQ * BATCH) / 128), 256>>>(inputs, emb, Wi, bvec);

    // 2. persistent LSTM recurrence
    cudaFuncSetAttribute(lstm_kernel, cudaFuncAttributeMaxDynamicSharedMemorySize, LSTM_SMEM);
    lstm_kernel<<<NBLK, 256, LSTM_SMEM>>>(Wh);

    // 3/4. dense tanh layers (fc1 reads k-major h)
    fc_tanh_kernel<64, 1><<<128, 256>>>((const float*)p_h,  W1, b1, (float*)p_y1);
    fc_tanh_kernel<1, 512><<<128, 256>>>((const float*)p_y1, W2, b2, (float*)p_y2);

    // 5. vocab projection
    logits_kernel<<<(VOCAB + 127) / 128, 128>>>((const float*)p_y2, W3, b3, (float*)p_lg);

    // 6. log_softmax
    logsoftmax_kernel<<<BATCH, 1024>>>((const float*)p_lg, out);
}